// round 1
// baseline (speedup 1.0000x reference)
#include <cuda_runtime.h>
#include <limits.h>

// Problem shape (fixed by setup_inputs): B=256, N=65536, half=32768.
#define NCOL   65536
#define HALF   32768
#define BDIM   1024
#define MAXB   1024   // safety headroom for partials

#define THRESH 0.01f
#define PENALTY 2.0f

__device__ float g_partials[MAXB];

__device__ __forceinline__ void chk(float v, int idx, int& tmin, int& tmax) {
    if (fabsf(v) > THRESH) {
        tmin = min(tmin, idx);
        tmax = max(tmax, idx);
    }
}

__global__ __launch_bounds__(BDIM)
void row_loss_kernel(const float* __restrict__ pred,
                     const float* __restrict__ lab)
{
    const int b = blockIdx.x;
    const size_t row = (size_t)b * NCOL;
    const float4* __restrict__ lr4 = (const float4*)(lab  + row);
    const float4* __restrict__ li4 = (const float4*)(lab  + row + HALF);
    const float4* __restrict__ pr4 = (const float4*)(pred + row);
    const float4* __restrict__ pi4 = (const float4*)(pred + row + HALF);

    __shared__ int s_min_r, s_max_r, s_min_i, s_max_i;
    if (threadIdx.x == 0) {
        s_min_r = INT_MAX; s_max_r = -1;
        s_min_i = INT_MAX; s_max_i = -1;
    }
    __syncthreads();

    // ---- Phase 1: first/last significant index of label real & imag halves ----
    int tmin_r = INT_MAX, tmax_r = -1;
    int tmin_i = INT_MAX, tmax_i = -1;

    #pragma unroll 4
    for (int j4 = threadIdx.x; j4 < HALF / 4; j4 += BDIM) {
        float4 r  = lr4[j4];
        float4 im = li4[j4];
        int base = j4 * 4;
        chk(r.x,  base + 0, tmin_r, tmax_r);
        chk(r.y,  base + 1, tmin_r, tmax_r);
        chk(r.z,  base + 2, tmin_r, tmax_r);
        chk(r.w,  base + 3, tmin_r, tmax_r);
        chk(im.x, base + 0, tmin_i, tmax_i);
        chk(im.y, base + 1, tmin_i, tmax_i);
        chk(im.z, base + 2, tmin_i, tmax_i);
        chk(im.w, base + 3, tmin_i, tmax_i);
    }
    // Warp-level pre-reduce to cut shared atomics 32x
    #pragma unroll
    for (int off = 16; off > 0; off >>= 1) {
        tmin_r = min(tmin_r, __shfl_xor_sync(0xFFFFFFFFu, tmin_r, off));
        tmax_r = max(tmax_r, __shfl_xor_sync(0xFFFFFFFFu, tmax_r, off));
        tmin_i = min(tmin_i, __shfl_xor_sync(0xFFFFFFFFu, tmin_i, off));
        tmax_i = max(tmax_i, __shfl_xor_sync(0xFFFFFFFFu, tmax_i, off));
    }
    if ((threadIdx.x & 31) == 0) {
        atomicMin(&s_min_r, tmin_r);
        atomicMax(&s_max_r, tmax_r);
        atomicMin(&s_min_i, tmin_i);
        atomicMax(&s_max_i, tmax_i);
    }
    __syncthreads();

    // any-mask handling: no significant element -> first=0, last=half-1 (weight all 1.0)
    const int fr = (s_max_r < 0) ? 0        : s_min_r;
    const int lr = (s_max_r < 0) ? HALF - 1 : s_max_r;
    const int fi = (s_max_i < 0) ? 0        : s_min_i;
    const int li = (s_max_i < 0) ? HALF - 1 : s_max_i;

    // ---- Phase 2: weighted MSE accumulation (label re-read hits L2) ----
    float acc = 0.0f;

    #pragma unroll 2
    for (int j4 = threadIdx.x; j4 < HALF / 4; j4 += BDIM) {
        float4 lrv = lr4[j4];
        float4 liv = li4[j4];
        float4 prv = pr4[j4];
        float4 piv = pi4[j4];
        int base = j4 * 4;

        #pragma unroll
        for (int k = 0; k < 4; k++) {
            float lrx = (&lrv.x)[k];
            float lix = (&liv.x)[k];
            float prx = (&prv.x)[k];
            float pix = (&piv.x)[k];
            int   j   = base + k;

            float dr   = prx - lrx;
            float di   = pix - lix;
            float lint = lrx * lrx + lix * lix;
            float pint = prx * prx + pix * pix;
            float dint = pint - lint;

            float wr = (j < fr || j > lr) ? PENALTY : 1.0f;
            float wi = (j < fi || j > li) ? PENALTY : 1.0f;

            acc += wr * dr * dr + wi * di * di + 50.0f * dint * dint;
        }
    }

    // ---- Block sum reduction ----
    __shared__ float s_warp[BDIM / 32];
    #pragma unroll
    for (int off = 16; off > 0; off >>= 1)
        acc += __shfl_xor_sync(0xFFFFFFFFu, acc, off);
    if ((threadIdx.x & 31) == 0)
        s_warp[threadIdx.x >> 5] = acc;
    __syncthreads();
    if (threadIdx.x < 32) {
        float v = (threadIdx.x < BDIM / 32) ? s_warp[threadIdx.x] : 0.0f;
        #pragma unroll
        for (int off = 16; off > 0; off >>= 1)
            v += __shfl_xor_sync(0xFFFFFFFFu, v, off);
        if (threadIdx.x == 0)
            g_partials[b] = v;
    }
}

__global__ void final_reduce_kernel(float* __restrict__ out, int B)
{
    __shared__ float s[256];
    float v = (threadIdx.x < B) ? g_partials[threadIdx.x] : 0.0f;
    s[threadIdx.x] = v;
    __syncthreads();
    #pragma unroll
    for (int st = 128; st > 0; st >>= 1) {
        if (threadIdx.x < st) s[threadIdx.x] += s[threadIdx.x + st];
        __syncthreads();
    }
    if (threadIdx.x == 0)
        out[0] = s[0] / ((float)HALF * (float)B);
}

extern "C" void kernel_launch(void* const* d_in, const int* in_sizes, int n_in,
                              void* d_out, int out_size)
{
    const float* pred = (const float*)d_in[0];
    const float* lab  = (const float*)d_in[1];
    float* out = (float*)d_out;

    const int B = in_sizes[0] / NCOL;   // 256 for this problem

    row_loss_kernel<<<B, BDIM>>>(pred, lab);
    final_reduce_kernel<<<1, 256>>>(out, B);
}

// round 3
// speedup vs baseline: 1.2398x; 1.2398x over previous
#include <cuda_runtime.h>
#include <limits.h>

// Problem shape (fixed by setup_inputs): B=256, N=65536, half=32768.
#define NCOL   65536
#define HALF   32768
#define BDIM   512
#define MAXB   1024

#define THRESH  0.01f
#define PENALTY 2.0f

__device__ float        g_partials[MAXB];
__device__ unsigned int g_counter = 0;

// ---- cache-policy load helpers (createpolicy + L2::cache_hint form) -------
__device__ __forceinline__ unsigned long long mk_policy_evict_last() {
    unsigned long long pol;
    asm("createpolicy.fractional.L2::evict_last.b64 %0, 1.0;" : "=l"(pol));
    return pol;
}
__device__ __forceinline__ unsigned long long mk_policy_evict_first() {
    unsigned long long pol;
    asm("createpolicy.fractional.L2::evict_first.b64 %0, 1.0;" : "=l"(pol));
    return pol;
}
__device__ __forceinline__ float4 ld_pol(const float4* p, unsigned long long pol) {
    float4 v;
    asm volatile("ld.global.nc.L2::cache_hint.v4.f32 {%0,%1,%2,%3}, [%4], %5;"
                 : "=f"(v.x), "=f"(v.y), "=f"(v.z), "=f"(v.w)
                 : "l"(p), "l"(pol));
    return v;
}

__device__ __forceinline__ void chk(float v, int idx, int& tmin, int& tmax) {
    if (fabsf(v) > THRESH) {
        tmin = min(tmin, idx);
        tmax = max(tmax, idx);
    }
}

__global__ __launch_bounds__(BDIM, 2)
void fused_loss_kernel(const float* __restrict__ pred,
                       const float* __restrict__ lab,
                       float* __restrict__ out,
                       int B)
{
    const int b = blockIdx.x;
    const size_t row = (size_t)b * NCOL;
    const float4* __restrict__ lr4 = (const float4*)(lab  + row);
    const float4* __restrict__ li4 = (const float4*)(lab  + row + HALF);
    const float4* __restrict__ pr4 = (const float4*)(pred + row);
    const float4* __restrict__ pi4 = (const float4*)(pred + row + HALF);

    const unsigned long long pol_keep   = mk_policy_evict_last();
    const unsigned long long pol_stream = mk_policy_evict_first();

    __shared__ int s_min_r, s_max_r, s_min_i, s_max_i;
    __shared__ bool s_is_last;
    if (threadIdx.x == 0) {
        s_min_r = INT_MAX; s_max_r = -1;
        s_min_i = INT_MAX; s_max_i = -1;
    }
    __syncthreads();

    // ---- Phase 1: first/last significant index of label halves --------------
    // Label loads tagged evict_last so the phase-2 re-read hits L2.
    int tmin_r = INT_MAX, tmax_r = -1;
    int tmin_i = INT_MAX, tmax_i = -1;

    #pragma unroll
    for (int it = 0; it < HALF / 4 / BDIM; it++) {          // 16 iters
        int j4 = threadIdx.x + it * BDIM;
        float4 r  = ld_pol(lr4 + j4, pol_keep);
        float4 im = ld_pol(li4 + j4, pol_keep);
        int base = j4 * 4;
        chk(r.x,  base + 0, tmin_r, tmax_r);
        chk(r.y,  base + 1, tmin_r, tmax_r);
        chk(r.z,  base + 2, tmin_r, tmax_r);
        chk(r.w,  base + 3, tmin_r, tmax_r);
        chk(im.x, base + 0, tmin_i, tmax_i);
        chk(im.y, base + 1, tmin_i, tmax_i);
        chk(im.z, base + 2, tmin_i, tmax_i);
        chk(im.w, base + 3, tmin_i, tmax_i);
    }
    #pragma unroll
    for (int off = 16; off > 0; off >>= 1) {
        tmin_r = min(tmin_r, __shfl_xor_sync(0xFFFFFFFFu, tmin_r, off));
        tmax_r = max(tmax_r, __shfl_xor_sync(0xFFFFFFFFu, tmax_r, off));
        tmin_i = min(tmin_i, __shfl_xor_sync(0xFFFFFFFFu, tmin_i, off));
        tmax_i = max(tmax_i, __shfl_xor_sync(0xFFFFFFFFu, tmax_i, off));
    }
    if ((threadIdx.x & 31) == 0) {
        atomicMin(&s_min_r, tmin_r);
        atomicMax(&s_max_r, tmax_r);
        atomicMin(&s_min_i, tmin_i);
        atomicMax(&s_max_i, tmax_i);
    }
    __syncthreads();

    const int fr = (s_max_r < 0) ? 0        : s_min_r;
    const int lr = (s_max_r < 0) ? HALF - 1 : s_max_r;
    const int fi = (s_max_i < 0) ? 0        : s_min_i;
    const int li = (s_max_i < 0) ? HALF - 1 : s_max_i;

    // ---- Phase 2: weighted MSE (label from L2, pred streamed) ---------------
    float acc = 0.0f;

    #pragma unroll 2
    for (int it = 0; it < HALF / 4 / BDIM; it++) {          // 16 iters
        int j4 = threadIdx.x + it * BDIM;
        float4 lrv = ld_pol(lr4 + j4, pol_stream);
        float4 liv = ld_pol(li4 + j4, pol_stream);
        float4 prv = ld_pol(pr4 + j4, pol_stream);
        float4 piv = ld_pol(pi4 + j4, pol_stream);
        int base = j4 * 4;

        #pragma unroll
        for (int k = 0; k < 4; k++) {
            float lrx = (&lrv.x)[k];
            float lix = (&liv.x)[k];
            float prx = (&prv.x)[k];
            float pix = (&piv.x)[k];
            int   j   = base + k;

            float dr   = prx - lrx;
            float di   = pix - lix;
            float lint = lrx * lrx + lix * lix;
            float pint = prx * prx + pix * pix;
            float dint = pint - lint;

            float wr = (j < fr || j > lr) ? PENALTY : 1.0f;
            float wi = (j < fi || j > li) ? PENALTY : 1.0f;

            acc += wr * dr * dr + wi * di * di + 50.0f * dint * dint;
        }
    }

    // ---- Block sum reduction -------------------------------------------------
    __shared__ float s_warp[BDIM / 32];
    #pragma unroll
    for (int off = 16; off > 0; off >>= 1)
        acc += __shfl_xor_sync(0xFFFFFFFFu, acc, off);
    if ((threadIdx.x & 31) == 0)
        s_warp[threadIdx.x >> 5] = acc;
    __syncthreads();
    if (threadIdx.x < 32) {
        float v = (threadIdx.x < BDIM / 32) ? s_warp[threadIdx.x] : 0.0f;
        #pragma unroll
        for (int off = 16; off > 0; off >>= 1)
            v += __shfl_xor_sync(0xFFFFFFFFu, v, off);
        if (threadIdx.x == 0)
            g_partials[b] = v;
    }

    // ---- Last CTA folds the 256 partials (threadfence-reduction pattern) ----
    if (threadIdx.x == 0) {
        __threadfence();                               // publish g_partials[b]
        unsigned int ticket = atomicAdd(&g_counter, 1u);
        s_is_last = (ticket == (unsigned int)(B - 1));
    }
    __syncthreads();

    if (s_is_last) {
        __threadfence();                               // observe all partials
        __shared__ float s_fin[256];
        if (threadIdx.x < 256)
            s_fin[threadIdx.x] = (threadIdx.x < B) ? g_partials[threadIdx.x] : 0.0f;
        __syncthreads();
        #pragma unroll
        for (int st = 128; st > 0; st >>= 1) {
            if (threadIdx.x < st) s_fin[threadIdx.x] += s_fin[threadIdx.x + st];
            __syncthreads();
        }
        if (threadIdx.x == 0) {
            out[0] = s_fin[0] / ((float)HALF * (float)B);
            g_counter = 0;                             // reset for graph replay
        }
    }
}

extern "C" void kernel_launch(void* const* d_in, const int* in_sizes, int n_in,
                              void* d_out, int out_size)
{
    const float* pred = (const float*)d_in[0];
    const float* lab  = (const float*)d_in[1];
    float* out = (float*)d_out;

    const int B = in_sizes[0] / NCOL;   // 256

    fused_loss_kernel<<<B, BDIM>>>(pred, lab, out, B);
}